// round 5
// baseline (speedup 1.0000x reference)
#include <cuda_runtime.h>
#include <math.h>

// Problem constants
#define T_     128
#define B_     64
#define IN_    128
#define H_     512
#define G_     2048   // 4*H
#define N_     2048
#define W_     64
#define R_     4
#define OUT_   128
#define KEYS_  320    // (R+1)*W
#define CTRL_  384    // IN + R*W
#define KTOT_  896    // CTRL + H
#define KSPLIT_ 8
#define KC_    112    // KTOT/KSPLIT
#define JT_    128
#define BS_    16     // batch elements per gates block
#define EPS_   1e-8f

// ------------------------- persistent device state -------------------------
__device__ float g_WT[KTOT_ * G_];        // combined [Wih;Whh] transposed: [k][j]
__device__ float g_WT2[H_ * 448];         // combined [Wout;Wkey] transposed: [k][j]
__device__ float g_bc[448];               // combined [bout;bkey]
__device__ float g_h[B_ * H_];
__device__ float g_c[B_ * H_];
__device__ float g_M[2][B_ * W_ * N_];    // [par][b][w][n]  (n fastest!)
__device__ float g_rw[2][B_ * N_ * R_];   // [par][b][n][r]
__device__ float g_usage[B_ * N_];
__device__ float g_gpart[KSPLIT_ * B_ * G_];
__device__ float g_hpart[8 * B_ * 448];   // heads partials [kc][b][j]
__device__ float g_keys[B_ * KEYS_];
__device__ float g_kinv[B_ * R_];         // 1/(||read_key||+eps)
__device__ float g_sim[B_ * R_ * N_];
__device__ float g_ww[B_ * N_];
__device__ float g_pmax[B_ * 8 * 4];      // softmax chunk partial max  [b][chunk][r]
__device__ float g_psum[B_ * 8 * 4];      // softmax chunk partial sum  [b][chunk][r]
__device__ float g_rvpart[4 * B_ * 256];  // [chunk][b][r*64+w]
__device__ float g_aminv[B_ * 4];
__device__ int   g_amini[B_ * 4];

// ------------------------- weight prep -------------------------
__global__ void k_t1(const float* __restrict__ Wih, const float* __restrict__ Whh) {
    int idx = blockIdx.x * 256 + threadIdx.x;
    if (idx >= KTOT_ * G_) return;
    int k = idx / G_, j = idx % G_;
    g_WT[idx] = (k < CTRL_) ? Wih[j * CTRL_ + k] : Whh[j * H_ + (k - CTRL_)];
}

__global__ void k_t2(const float* __restrict__ Wout, const float* __restrict__ bout,
                     const float* __restrict__ Wkey, const float* __restrict__ bkey) {
    int idx = blockIdx.x * 256 + threadIdx.x;
    if (idx < H_ * 448) {
        int k = idx / 448, j = idx % 448;
        g_WT2[idx] = (j < OUT_) ? Wout[j * H_ + k] : Wkey[(j - OUT_) * H_ + k];
    }
    if (idx < 448) g_bc[idx] = (idx < OUT_) ? bout[idx] : bkey[idx - OUT_];
}

__global__ void k_init() {
    int idx = blockIdx.x * 256 + threadIdx.x;            // covers B*W*N = 8388608
    g_M[0][idx] = 1e-6f;
    if (idx < B_ * N_ * R_) g_rw[0][idx] = 0.f;
    if (idx < B_ * N_)     { g_usage[idx] = 0.f; g_ww[idx] = 0.f; }
    if (idx < B_ * H_)     { g_h[idx] = 0.f; g_c[idx] = 0.f; }
    if (idx < 4 * B_ * 256)  g_rvpart[idx] = 0.f;
    if (idx < B_ * 4)      { g_aminv[idx] = 0.f; g_amini[idx] = (idx & 3) * 512; }
}

// ------------------------- gates GEMM (split-K, split-B) -------------------
// grid (16 j-tiles, 8 k-chunks, 4 b-splits), 128 threads.
// Thread (tj,tb) computes a 4j x 4b register tile: 2 LDS128 + 16 FFMA per k.
__global__ __launch_bounds__(128) void k_gates(const float* __restrict__ x_seq, int t, int par) {
    __shared__ __align__(16) float Xs[KC_][BS_];
    __shared__ __align__(16) float Ws[16][JT_];
    int tid = threadIdx.x;
    int tj  = tid & 31;     // 32 j-groups of 4
    int tb  = tid >> 5;     // 4 b-groups of 4
    int j0  = blockIdx.x * JT_;
    int kc  = blockIdx.y;
    int k0  = kc * KC_;
    int b0  = blockIdx.z * BS_;

    for (int idx = tid; idx < BS_ * KC_; idx += 128) {
        int kk = idx / BS_, b = idx % BS_;
        int k = k0 + kk;
        int bg = b0 + b;
        float v;
        if (k < IN_)        v = x_seq[(t * B_ + bg) * IN_ + k];
        else if (k < CTRL_) {
            int o = bg * 256 + (k - IN_);
            v = g_rvpart[o] + g_rvpart[B_ * 256 + o] +
                g_rvpart[2 * B_ * 256 + o] + g_rvpart[3 * B_ * 256 + o];
        } else              v = g_h[bg * H_ + (k - CTRL_)];
        Xs[kk][b] = v;
    }
    __syncthreads();

    float4 acc[4];
#pragma unroll
    for (int i = 0; i < 4; i++) acc[i] = make_float4(0.f, 0.f, 0.f, 0.f);

    for (int ks = 0; ks < KC_; ks += 16) {
        if (ks) __syncthreads();
#pragma unroll
        for (int i = 0; i < 16; i++)
            Ws[i][tid] = g_WT[(k0 + ks + i) * G_ + j0 + tid];
        __syncthreads();
#pragma unroll
        for (int i = 0; i < 16; i++) {
            float4 w4 = *(const float4*)&Ws[i][tj * 4];
            float4 x4 = *(const float4*)&Xs[ks + i][tb * 4];
            acc[0].x += x4.x * w4.x; acc[0].y += x4.x * w4.y;
            acc[0].z += x4.x * w4.z; acc[0].w += x4.x * w4.w;
            acc[1].x += x4.y * w4.x; acc[1].y += x4.y * w4.y;
            acc[1].z += x4.y * w4.z; acc[1].w += x4.y * w4.w;
            acc[2].x += x4.z * w4.x; acc[2].y += x4.z * w4.y;
            acc[2].z += x4.z * w4.z; acc[2].w += x4.z * w4.w;
            acc[3].x += x4.w * w4.x; acc[3].y += x4.w * w4.y;
            acc[3].z += x4.w * w4.z; acc[3].w += x4.w * w4.w;
        }
    }
    float* gp = g_gpart + kc * (B_ * G_);
#pragma unroll
    for (int bb = 0; bb < 4; bb++)
        *(float4*)&gp[(b0 + tb * 4 + bb) * G_ + j0 + tj * 4] = acc[bb];
}

// ------------------------- reduce partials + LSTM cell ---------------------
__global__ void k_cell(const float* __restrict__ bih, const float* __restrict__ bhh) {
    int gid = blockIdx.x * blockDim.x + threadIdx.x;   // B*H = 32768
    int b = gid >> 9, u = gid & 511;
    float s[4];
#pragma unroll
    for (int q = 0; q < 4; q++) {
        int col = q * H_ + u;
        float v = bih[col] + bhh[col];
#pragma unroll
        for (int kc = 0; kc < KSPLIT_; kc++)
            v += g_gpart[kc * (B_ * G_) + b * G_ + col];
        s[q] = v;
    }
    float ig = 1.f / (1.f + expf(-s[0]));
    float fg = 1.f / (1.f + expf(-s[1]));
    float gg = tanhf(s[2]);
    float og = 1.f / (1.f + expf(-s[3]));
    float c  = fg * g_c[gid] + ig * gg;
    g_c[gid] = c;
    g_h[gid] = og * tanhf(c);
}

// ------------------------- heads GEMM (split-K, split-B) -------------------
__global__ __launch_bounds__(112) void k_headg() {
    __shared__ __align__(16) float Hs[64][BS_];
    __shared__ float Ws[8][112];
    int tid = threadIdx.x;
    int j   = blockIdx.x * 112 + tid;
    int k0  = blockIdx.y * 64;
    int b0  = blockIdx.z * BS_;

    for (int idx = tid; idx < BS_ * 64; idx += 112) {
        int kk = idx / BS_, b = idx % BS_;
        Hs[kk][b] = g_h[(b0 + b) * H_ + k0 + kk];
    }
    __syncthreads();

    float4 acc[4];
#pragma unroll
    for (int i = 0; i < 4; i++) acc[i] = make_float4(0.f, 0.f, 0.f, 0.f);

    for (int ks = 0; ks < 64; ks += 8) {
        if (ks) __syncthreads();
#pragma unroll
        for (int i = 0; i < 8; i++)
            Ws[i][tid] = g_WT2[(k0 + ks + i) * 448 + j];
        __syncthreads();
#pragma unroll
        for (int i = 0; i < 8; i++) {
            float w = Ws[i][tid];
            const float4* xrow = (const float4*)&Hs[ks + i][0];
#pragma unroll
            for (int b4 = 0; b4 < 4; b4++) {
                float4 x = xrow[b4];
                acc[b4].x += x.x * w; acc[b4].y += x.y * w;
                acc[b4].z += x.z * w; acc[b4].w += x.w * w;
            }
        }
    }
    float* hp = g_hpart + blockIdx.y * (B_ * 448);
#pragma unroll
    for (int b4 = 0; b4 < 4; b4++) {
        hp[(b0 + 4 * b4 + 0) * 448 + j] = acc[b4].x;
        hp[(b0 + 4 * b4 + 1) * 448 + j] = acc[b4].y;
        hp[(b0 + 4 * b4 + 2) * 448 + j] = acc[b4].z;
        hp[(b0 + 4 * b4 + 3) * 448 + j] = acc[b4].w;
    }
}

// -------------------- heads reduce + out + keys + key norms ----------------
__global__ void k_headred(float* __restrict__ out, int t) {
    int b = blockIdx.x, tid = threadIdx.x;  // 448 threads
    __shared__ float skey[KEYS_];
    float v = g_bc[tid];
#pragma unroll
    for (int kc = 0; kc < 8; kc++)
        v += g_hpart[kc * (B_ * 448) + b * 448 + tid];
    if (tid < OUT_) out[(t * B_ + b) * OUT_ + tid] = v;
    else { g_keys[b * KEYS_ + (tid - OUT_)] = v; skey[tid - OUT_] = v; }
    __syncthreads();
    if (tid < 128) {
        int r = tid >> 5, lane = tid & 31;
        float a = skey[r * 64 + lane], c2 = skey[r * 64 + lane + 32];
        float ssq = a * a + c2 * c2;
#pragma unroll
        for (int o = 16; o; o >>= 1) ssq += __shfl_down_sync(0xffffffffu, ssq, o);
        if (lane == 0) g_kinv[b * R_ + r] = 1.f / (sqrtf(ssq) + EPS_);
    }
}

// --- fused: cosine sims + softmax chunk partials + M rewrite + argmin fin --
// grid (8 n-tiles, 64 b), 256 threads; thread owns one n, M column in regs.
__global__ __launch_bounds__(256) void k_simwrite(const float* __restrict__ alpha_p, int par) {
    int b = blockIdx.y;
    int tid = threadIdx.x;
    int ch = blockIdx.x;
    int n = ch * 256 + tid;
    __shared__ float sk[5 * 64];
    __shared__ float skinv[4];
    __shared__ float s_sa;
    __shared__ int s_amin;
    __shared__ float sred[8][4];
    __shared__ float sbmax[4];
    for (int i = tid; i < KEYS_; i += 256) sk[i] = g_keys[b * KEYS_ + i];
    if (tid < 4) skinv[tid] = g_kinv[b * R_ + tid];
    if (tid == 4) s_sa = 1.f / (1.f + expf(-*alpha_p));
    if (tid == 5) {
        float bv = g_aminv[b * 4]; int bi = g_amini[b * 4];
#pragma unroll
        for (int c2 = 1; c2 < 4; c2++) {
            float v2 = g_aminv[b * 4 + c2]; int i2 = g_amini[b * 4 + c2];
            if (v2 < bv || (v2 == bv && i2 < bi)) { bv = v2; bi = i2; }
        }
        s_amin = bi;
    }
    __syncthreads();

    const float* Mold = g_M[par]     + b * (W_ * N_) + n;
    float*       Mnew = g_M[par ^ 1] + b * (W_ * N_) + n;
    float m[64];
    float ss = 0.f, d0 = 0.f, d1 = 0.f, d2 = 0.f, d3 = 0.f;
#pragma unroll
    for (int w = 0; w < 64; w++) {
        float mv = Mold[w * N_];
        m[w] = mv;
        ss += mv * mv;
        d0 += mv * sk[w];       d1 += mv * sk[64 + w];
        d2 += mv * sk[128 + w]; d3 += mv * sk[192 + w];
    }
    float minv = 1.f / (sqrtf(ss) + EPS_);
    float s4[4];
    s4[0] = d0 * skinv[0] * minv;
    s4[1] = d1 * skinv[1] * minv;
    s4[2] = d2 * skinv[2] * minv;
    s4[3] = d3 * skinv[3] * minv;
    g_sim[(b * R_ + 0) * N_ + n] = s4[0];
    g_sim[(b * R_ + 1) * N_ + n] = s4[1];
    g_sim[(b * R_ + 2) * N_ + n] = s4[2];
    g_sim[(b * R_ + 3) * N_ + n] = s4[3];

    // ---- softmax chunk partials: max & sum(exp(v-max)) over 256 n, 4 r ----
    int warp = tid >> 5, lane = tid & 31;
    float mx4[4];
#pragma unroll
    for (int r = 0; r < 4; r++) {
        float mv = s4[r];
#pragma unroll
        for (int o = 16; o; o >>= 1) mv = fmaxf(mv, __shfl_xor_sync(0xffffffffu, mv, o));
        mx4[r] = mv;
    }
    if (lane < 4) sred[warp][lane] = mx4[lane];
    __syncthreads();
    if (tid < 4) {
        float mv = sred[0][tid];
#pragma unroll
        for (int w2 = 1; w2 < 8; w2++) mv = fmaxf(mv, sred[w2][tid]);
        sbmax[tid] = mv;
    }
    __syncthreads();
    float sm4[4];
#pragma unroll
    for (int r = 0; r < 4; r++) {
        float e = expf(s4[r] - sbmax[r]);
#pragma unroll
        for (int o = 16; o; o >>= 1) e += __shfl_xor_sync(0xffffffffu, e, o);
        sm4[r] = e;
    }
    __syncthreads();
    if (lane < 4) sred[warp][lane] = sm4[lane];
    __syncthreads();
    if (tid < 4) {
        float sv = sred[0][tid];
#pragma unroll
        for (int w2 = 1; w2 < 8; w2++) sv += sred[w2][tid];
        g_pmax[(b * 8 + ch) * 4 + tid] = sbmax[tid];
        g_psum[(b * 8 + ch) * 4 + tid] = sv;
    }

    // ---- M rewrite + ww ----
    const float4 rw4 = *(const float4*)&g_rw[par][(b * N_ + n) * 4];
    float lu = (n == s_amin) ? 1.f : 0.f;
    float sa = s_sa;
    float ww = sa * (rw4.x + rw4.y + rw4.z + rw4.w) + (1.f - sa) * lu;
    g_ww[b * N_ + n] = ww;
    float keep = 1.f - lu;
#pragma unroll
    for (int w = 0; w < 64; w++)
        Mnew[w * N_] = m[w] * keep + ww * sk[256 + w];
}

// - fused: softmax finalize + rw write + usage + argmin + read_vec partials -
// grid (4 n-chunks of 512, 64 b), 256 threads
__global__ __launch_bounds__(256) void k_usage_read(const float* __restrict__ gamma_p, int par) {
    int ch = blockIdx.x, b = blockIdx.y;
    int n0 = ch * 512;
    int tid = threadIdx.x;
    __shared__ __align__(16) float srwT[4][512];
    __shared__ float smv[256];
    __shared__ int   smi[256];
    __shared__ float sgmax[4], sginv[4];
    if (tid < 4) {
        int r = tid;
        float mx = -3.4e38f;
#pragma unroll
        for (int c = 0; c < 8; c++) mx = fmaxf(mx, g_pmax[(b * 8 + c) * 4 + r]);
        float sv = 0.f;
#pragma unroll
        for (int c = 0; c < 8; c++)
            sv += g_psum[(b * 8 + c) * 4 + r] * expf(g_pmax[(b * 8 + c) * 4 + r] - mx);
        sgmax[r] = mx;
        sginv[r] = 1.f / sv;
    }
    __syncthreads();

    float* rwn = g_rw[par ^ 1];
    float gamma = *gamma_p;
    float lmin = 3.4e38f; int lidx = 0;
#pragma unroll
    for (int i = 0; i < 2; i++) {
        int nl = tid + i * 256;
        int n = n0 + nl;
        float4 rw4;
        rw4.x = expf(g_sim[(b * R_ + 0) * N_ + n] - sgmax[0]) * sginv[0];
        rw4.y = expf(g_sim[(b * R_ + 1) * N_ + n] - sgmax[1]) * sginv[1];
        rw4.z = expf(g_sim[(b * R_ + 2) * N_ + n] - sgmax[2]) * sginv[2];
        rw4.w = expf(g_sim[(b * R_ + 3) * N_ + n] - sgmax[3]) * sginv[3];
        *(float4*)&rwn[(b * N_ + n) * 4] = rw4;
        srwT[0][nl] = rw4.x; srwT[1][nl] = rw4.y; srwT[2][nl] = rw4.z; srwT[3][nl] = rw4.w;
        float un = gamma * g_usage[b * N_ + n] + (rw4.x + rw4.y + rw4.z + rw4.w) + g_ww[b * N_ + n];
        g_usage[b * N_ + n] = un;
        if (un < lmin) { lmin = un; lidx = n; }
    }
    smv[tid] = lmin; smi[tid] = lidx;
    __syncthreads();
    for (int s = 128; s > 0; s >>= 1) {
        if (tid < s) {
            float v2 = smv[tid + s]; int i2 = smi[tid + s];
            if (v2 < smv[tid] || (v2 == smv[tid] && i2 < smi[tid])) { smv[tid] = v2; smi[tid] = i2; }
        }
        __syncthreads();
    }
    if (tid == 0) { g_aminv[b * 4 + ch] = smv[0]; g_amini[b * 4 + ch] = smi[0]; }

    // read-vector partials: rv_part[r][w] = sum_{n in chunk} rw[n][r] * M[b][w][n]
    int warp = tid >> 5, lane = tid & 31;
    const float* Mb = g_M[par] + b * (W_ * N_);
#pragma unroll
    for (int wi = 0; wi < 8; wi++) {
        int w = warp * 8 + wi;
        const float4* mp = (const float4*)(Mb + w * N_ + n0);
        float a0 = 0.f, a1 = 0.f, a2 = 0.f, a3 = 0.f;
#pragma unroll
        for (int nn = 0; nn < 4; nn++) {
            int q = lane + nn * 32;
            float4 m4 = mp[q];
            float4 r0 = ((const float4*)srwT[0])[q];
            float4 r1 = ((const float4*)srwT[1])[q];
            float4 r2 = ((const float4*)srwT[2])[q];
            float4 r3 = ((const float4*)srwT[3])[q];
            a0 += m4.x * r0.x + m4.y * r0.y + m4.z * r0.z + m4.w * r0.w;
            a1 += m4.x * r1.x + m4.y * r1.y + m4.z * r1.z + m4.w * r1.w;
            a2 += m4.x * r2.x + m4.y * r2.y + m4.z * r2.z + m4.w * r2.w;
            a3 += m4.x * r3.x + m4.y * r3.y + m4.z * r3.z + m4.w * r3.w;
        }
#pragma unroll
        for (int o = 16; o; o >>= 1) {
            a0 += __shfl_down_sync(0xffffffffu, a0, o);
            a1 += __shfl_down_sync(0xffffffffu, a1, o);
            a2 += __shfl_down_sync(0xffffffffu, a2, o);
            a3 += __shfl_down_sync(0xffffffffu, a3, o);
        }
        if (lane == 0) {
            float* rp = g_rvpart + ch * (B_ * 256) + b * 256;
            rp[0 * 64 + w] = a0; rp[64 + w] = a1; rp[128 + w] = a2; rp[192 + w] = a3;
        }
    }
}

// ------------------------- launch ------------------------------------------
extern "C" void kernel_launch(void* const* d_in, const int* in_sizes, int n_in,
                              void* d_out, int out_size) {
    const float* x_seq = (const float*)d_in[0];
    const float* Wih   = (const float*)d_in[1];
    const float* Whh   = (const float*)d_in[2];
    const float* bih   = (const float*)d_in[3];
    const float* bhh   = (const float*)d_in[4];
    const float* Wout  = (const float*)d_in[5];
    const float* bout  = (const float*)d_in[6];
    const float* Wkey  = (const float*)d_in[7];
    const float* bkey  = (const float*)d_in[8];
    const float* alpha = (const float*)d_in[9];
    const float* gamma = (const float*)d_in[10];
    float* out = (float*)d_out;

    k_t1<<<(KTOT_ * G_ + 255) / 256, 256>>>(Wih, Whh);
    k_t2<<<(H_ * 448 + 255) / 256, 256>>>(Wout, bout, Wkey, bkey);
    k_init<<<(B_ * W_ * N_) / 256, 256>>>();

    for (int t = 0; t < T_; t++) {
        int par = t & 1;
        k_gates<<<dim3(G_ / JT_, KSPLIT_, B_ / BS_), JT_>>>(x_seq, t, par);
        k_cell<<<(B_ * H_) / 256, 256>>>(bih, bhh);
        k_headg<<<dim3(4, 8, B_ / BS_), 112>>>();
        k_headred<<<B_, 448>>>(out, t);
        k_simwrite<<<dim3(N_ / 256, B_), 256>>>(alpha, par);
        k_usage_read<<<dim3(4, B_), 256>>>(gamma, par);
    }
}

// round 6
// speedup vs baseline: 1.0233x; 1.0233x over previous
#include <cuda_runtime.h>
#include <math.h>

// Problem constants
#define T_     128
#define B_     64
#define IN_    128
#define H_     512
#define G_     2048   // 4*H
#define N_     2048
#define W_     64
#define R_     4
#define OUT_   128
#define KEYS_  320    // (R+1)*W
#define CTRL_  384    // IN + R*W
#define KTOT_  896    // CTRL + H
#define KSPLIT_ 16
#define KC_    56     // KTOT/KSPLIT
#define JT_    128
#define BS_    16     // batch elements per gates block
#define EPS_   1e-8f

// ------------------------- persistent device state -------------------------
__device__ float g_WT[KTOT_ * G_];        // combined [Wih;Whh] transposed: [k][j]
__device__ float g_WT2[H_ * 448];         // combined [Wout;Wkey] transposed: [k][j]
__device__ float g_bc[448];               // combined [bout;bkey]
__device__ float g_h[B_ * H_];
__device__ float g_c[B_ * H_];
__device__ float g_M[2][B_ * W_ * N_];    // [par][b][w][n]  (n fastest!)
__device__ float g_usage[B_ * N_];
__device__ float g_gpart[KSPLIT_ * B_ * G_];
__device__ float g_hpart[8 * B_ * 448];   // heads partials [kc][b][j]
__device__ float g_kinv[B_ * R_];         // 1/(||read_key||+eps)
__device__ float g_eraw[B_ * N_ * R_];    // exp(sim - cmax_ch), [b][n][r]
__device__ float g_rwsum[B_ * N_];        // normalized sum_r rw[r][n]
__device__ float g_ww[B_ * N_];
__device__ float g_pmax[B_ * 8 * 4];      // softmax chunk partial max  [b][ch][r]
__device__ float g_psum[B_ * 8 * 4];      // softmax chunk partial sum  [b][ch][r]
__device__ float g_scale[B_ * 8 * 4];     // exp(cmax-gmax)/gsum        [b][ch][r]
__device__ float g_rvpart[8 * B_ * 256];  // unnormalized rv partials [ch][b][r*64+w]
__device__ float g_aminv[B_ * 4];
__device__ int   g_amini[B_ * 4];

// ------------------------- weight prep -------------------------
__global__ void k_t1(const float* __restrict__ Wih, const float* __restrict__ Whh) {
    int idx = blockIdx.x * 256 + threadIdx.x;
    if (idx >= KTOT_ * G_) return;
    int k = idx / G_, j = idx % G_;
    g_WT[idx] = (k < CTRL_) ? Wih[j * CTRL_ + k] : Whh[j * H_ + (k - CTRL_)];
}

__global__ void k_t2(const float* __restrict__ Wout, const float* __restrict__ bout,
                     const float* __restrict__ Wkey, const float* __restrict__ bkey) {
    int idx = blockIdx.x * 256 + threadIdx.x;
    if (idx < H_ * 448) {
        int k = idx / 448, j = idx % 448;
        g_WT2[idx] = (j < OUT_) ? Wout[j * H_ + k] : Wkey[(j - OUT_) * H_ + k];
    }
    if (idx < 448) g_bc[idx] = (idx < OUT_) ? bout[idx] : bkey[idx - OUT_];
}

__global__ void k_init() {
    int idx = blockIdx.x * 256 + threadIdx.x;            // covers B*W*N = 8388608
    g_M[0][idx] = 1e-6f;
    if (idx < B_ * N_ * R_)  g_eraw[idx] = 0.f;
    if (idx < B_ * N_)     { g_usage[idx] = 0.f; g_ww[idx] = 0.f; g_rwsum[idx] = 0.f; }
    if (idx < B_ * H_)     { g_h[idx] = 0.f; g_c[idx] = 0.f; }
    if (idx < 8 * B_ * 256)  g_rvpart[idx] = 0.f;
    if (idx < B_ * 8 * 4)    g_scale[idx] = 0.f;
    if (idx < B_ * 4)      { g_aminv[idx] = 0.f; g_amini[idx] = (idx & 3) * 512; }
}

// ------------------------- gates GEMM (split-K 16, split-B 4) --------------
// grid (16 j-tiles, 16 k-chunks, 4 b-splits) = 1024 blocks, 128 threads.
// Thread (tj,tb) computes a 4j x 4b register tile.
__global__ __launch_bounds__(128) void k_gates(const float* __restrict__ x_seq, int t) {
    __shared__ __align__(16) float Xs[KC_][BS_];
    __shared__ __align__(16) float Ws[8][JT_];
    int tid = threadIdx.x;
    int tj  = tid & 31;     // 32 j-groups of 4
    int tb  = tid >> 5;     // 4 b-groups of 4
    int j0  = blockIdx.x * JT_;
    int kc  = blockIdx.y;
    int k0  = kc * KC_;
    int b0  = blockIdx.z * BS_;

    for (int idx = tid; idx < BS_ * KC_; idx += 128) {
        int kk = idx / BS_, b = idx % BS_;
        int k = k0 + kk;
        int bg = b0 + b;
        float v;
        if (k < IN_)        v = x_seq[(t * B_ + bg) * IN_ + k];
        else if (k < CTRL_) {
            int o = k - IN_;
            int r = o >> 6;
            v = 0.f;
#pragma unroll
            for (int ch = 0; ch < 8; ch++)
                v += g_rvpart[(ch * B_ + bg) * 256 + o] * g_scale[bg * 32 + ch * 4 + r];
        } else              v = g_h[bg * H_ + (k - CTRL_)];
        Xs[kk][b] = v;
    }
    __syncthreads();

    float4 acc[4];
#pragma unroll
    for (int i = 0; i < 4; i++) acc[i] = make_float4(0.f, 0.f, 0.f, 0.f);

    for (int ks = 0; ks < KC_; ks += 8) {
        if (ks) __syncthreads();
#pragma unroll
        for (int i = 0; i < 8; i++)
            Ws[i][tid] = g_WT[(k0 + ks + i) * G_ + j0 + tid];
        __syncthreads();
#pragma unroll
        for (int i = 0; i < 8; i++) {
            float4 w4 = *(const float4*)&Ws[i][tj * 4];
            float4 x4 = *(const float4*)&Xs[ks + i][tb * 4];
            acc[0].x += x4.x * w4.x; acc[0].y += x4.x * w4.y;
            acc[0].z += x4.x * w4.z; acc[0].w += x4.x * w4.w;
            acc[1].x += x4.y * w4.x; acc[1].y += x4.y * w4.y;
            acc[1].z += x4.y * w4.z; acc[1].w += x4.y * w4.w;
            acc[2].x += x4.z * w4.x; acc[2].y += x4.z * w4.y;
            acc[2].z += x4.z * w4.z; acc[2].w += x4.z * w4.w;
            acc[3].x += x4.w * w4.x; acc[3].y += x4.w * w4.y;
            acc[3].z += x4.w * w4.z; acc[3].w += x4.w * w4.w;
        }
    }
    float* gp = g_gpart + kc * (B_ * G_);
#pragma unroll
    for (int bb = 0; bb < 4; bb++)
        *(float4*)&gp[(b0 + tb * 4 + bb) * G_ + j0 + tj * 4] = acc[bb];
}

// ------------------------- reduce partials + LSTM cell ---------------------
__global__ void k_cell(const float* __restrict__ bih, const float* __restrict__ bhh) {
    int gid = blockIdx.x * blockDim.x + threadIdx.x;   // B*H = 32768
    int b = gid >> 9, u = gid & 511;
    float s[4];
#pragma unroll
    for (int q = 0; q < 4; q++) {
        int col = q * H_ + u;
        float v = bih[col] + bhh[col];
#pragma unroll
        for (int kc = 0; kc < KSPLIT_; kc++)
            v += g_gpart[kc * (B_ * G_) + b * G_ + col];
        s[q] = v;
    }
    float ig = 1.f / (1.f + expf(-s[0]));
    float fg = 1.f / (1.f + expf(-s[1]));
    float gg = tanhf(s[2]);
    float og = 1.f / (1.f + expf(-s[3]));
    float c  = fg * g_c[gid] + ig * gg;
    g_c[gid] = c;
    g_h[gid] = og * tanhf(c);
}

// ------------------------- heads GEMM (split-K, split-B) -------------------
__global__ __launch_bounds__(112) void k_headg() {
    __shared__ __align__(16) float Hs[64][BS_];
    __shared__ float Ws[8][112];
    int tid = threadIdx.x;
    int j   = blockIdx.x * 112 + tid;
    int k0  = blockIdx.y * 64;
    int b0  = blockIdx.z * BS_;

    for (int idx = tid; idx < BS_ * 64; idx += 112) {
        int kk = idx / BS_, b = idx % BS_;
        Hs[kk][b] = g_h[(b0 + b) * H_ + k0 + kk];
    }
    __syncthreads();

    float4 acc[4];
#pragma unroll
    for (int i = 0; i < 4; i++) acc[i] = make_float4(0.f, 0.f, 0.f, 0.f);

    for (int ks = 0; ks < 64; ks += 8) {
        if (ks) __syncthreads();
#pragma unroll
        for (int i = 0; i < 8; i++)
            Ws[i][tid] = g_WT2[(k0 + ks + i) * 448 + j];
        __syncthreads();
#pragma unroll
        for (int i = 0; i < 8; i++) {
            float w = Ws[i][tid];
            const float4* xrow = (const float4*)&Hs[ks + i][0];
#pragma unroll
            for (int b4 = 0; b4 < 4; b4++) {
                float4 x = xrow[b4];
                acc[b4].x += x.x * w; acc[b4].y += x.y * w;
                acc[b4].z += x.z * w; acc[b4].w += x.w * w;
            }
        }
    }
    float* hp = g_hpart + blockIdx.y * (B_ * 448);
#pragma unroll
    for (int b4 = 0; b4 < 4; b4++) {
        hp[(b0 + 4 * b4 + 0) * 448 + j] = acc[b4].x;
        hp[(b0 + 4 * b4 + 1) * 448 + j] = acc[b4].y;
        hp[(b0 + 4 * b4 + 2) * 448 + j] = acc[b4].z;
        hp[(b0 + 4 * b4 + 3) * 448 + j] = acc[b4].w;
    }
}

// ---- mega: keys reduce + out + norms + sims + softmax partials + M write
// ---- + unnormalized read-vec partials.  grid (8 n-chunks, 64 b), 256 thr.
__global__ __launch_bounds__(256) void k_simwrite(float* __restrict__ out, int t,
                                                  const float* __restrict__ alpha_p, int par) {
    int b = blockIdx.y;
    int ch = blockIdx.x;
    int tid = threadIdx.x;
    int n = ch * 256 + tid;
    __shared__ float skey[KEYS_];
    __shared__ float skinv[4];
    __shared__ float s_sa;
    __shared__ int s_amin;
    __shared__ float sred[8][4];
    __shared__ float sbmax[4];
    __shared__ __align__(16) float se[4][256];

    // keys reduce from hpart
    for (int i = tid; i < KEYS_; i += 256) {
        float v = g_bc[OUT_ + i];
#pragma unroll
        for (int kc = 0; kc < 8; kc++)
            v += g_hpart[kc * (B_ * 448) + b * 448 + OUT_ + i];
        skey[i] = v;
    }
    // out write (once, by ch==0 blocks)
    if (ch == 0 && tid < OUT_) {
        float v = g_bc[tid];
#pragma unroll
        for (int kc = 0; kc < 8; kc++)
            v += g_hpart[kc * (B_ * 448) + b * 448 + tid];
        out[(t * B_ + b) * OUT_ + tid] = v;
    }
    if (tid == 254) s_sa = 1.f / (1.f + expf(-*alpha_p));
    if (tid == 255) {
        float bv = g_aminv[b * 4]; int bi = g_amini[b * 4];
#pragma unroll
        for (int c2 = 1; c2 < 4; c2++) {
            float v2 = g_aminv[b * 4 + c2]; int i2 = g_amini[b * 4 + c2];
            if (v2 < bv || (v2 == bv && i2 < bi)) { bv = v2; bi = i2; }
        }
        s_amin = bi;
    }
    __syncthreads();
    // key norms
    if (tid < 128) {
        int r = tid >> 5, lane = tid & 31;
        float a = skey[r * 64 + lane], c2 = skey[r * 64 + lane + 32];
        float ssq = a * a + c2 * c2;
#pragma unroll
        for (int o = 16; o; o >>= 1) ssq += __shfl_down_sync(0xffffffffu, ssq, o);
        if (lane == 0) skinv[r] = 1.f / (sqrtf(ssq) + EPS_);
    }
    __syncthreads();

    const float* Mold = g_M[par]     + b * (W_ * N_) + n;
    float*       Mnew = g_M[par ^ 1] + b * (W_ * N_) + n;
    float m[64];
    float ss = 0.f, d0 = 0.f, d1 = 0.f, d2 = 0.f, d3 = 0.f;
#pragma unroll
    for (int w = 0; w < 64; w++) {
        float mv = Mold[w * N_];
        m[w] = mv;
        ss += mv * mv;
        d0 += mv * skey[w];       d1 += mv * skey[64 + w];
        d2 += mv * skey[128 + w]; d3 += mv * skey[192 + w];
    }
    float minv = 1.f / (sqrtf(ss) + EPS_);
    float s4[4];
    s4[0] = d0 * skinv[0] * minv;
    s4[1] = d1 * skinv[1] * minv;
    s4[2] = d2 * skinv[2] * minv;
    s4[3] = d3 * skinv[3] * minv;

    // chunk softmax partials: max & sum(exp(v-max)) over 256 n, 4 r
    int warp = tid >> 5, lane = tid & 31;
#pragma unroll
    for (int r = 0; r < 4; r++) {
        float mv = s4[r];
#pragma unroll
        for (int o = 16; o; o >>= 1) mv = fmaxf(mv, __shfl_xor_sync(0xffffffffu, mv, o));
        if (lane == 0) sred[warp][r] = mv;
    }
    __syncthreads();
    if (tid < 4) {
        float mv = sred[0][tid];
#pragma unroll
        for (int w2 = 1; w2 < 8; w2++) mv = fmaxf(mv, sred[w2][tid]);
        sbmax[tid] = mv;
    }
    __syncthreads();
    float e4[4];
#pragma unroll
    for (int r = 0; r < 4; r++) {
        float e = expf(s4[r] - sbmax[r]);
        e4[r] = e;
        se[r][tid] = e;
#pragma unroll
        for (int o = 16; o; o >>= 1) e += __shfl_xor_sync(0xffffffffu, e, o);
        if (lane == 0) sred[warp][r] = e;
    }
    *(float4*)&g_eraw[(b * N_ + n) * 4] = make_float4(e4[0], e4[1], e4[2], e4[3]);
    __syncthreads();
    if (tid < 4) {
        float sv = sred[0][tid];
#pragma unroll
        for (int w2 = 1; w2 < 8; w2++) sv += sred[w2][tid];
        g_pmax[(b * 8 + ch) * 4 + tid] = sbmax[tid];
        g_psum[(b * 8 + ch) * 4 + tid] = sv;
    }

    // M rewrite + ww (uses previous step's normalized rwsum)
    float rs = g_rwsum[b * N_ + n];
    float lu = (n == s_amin) ? 1.f : 0.f;
    float sa = s_sa;
    float ww = sa * rs + (1.f - sa) * lu;
    g_ww[b * N_ + n] = ww;
    float keep = 1.f - lu;
#pragma unroll
    for (int w = 0; w < 64; w++)
        Mnew[w * N_] = m[w] * keep + ww * skey[256 + w];

    // unnormalized read-vec partials over this chunk (L1/L2-hot M re-read)
    const float* Mb = g_M[par] + b * (W_ * N_);
#pragma unroll
    for (int wi = 0; wi < 8; wi++) {
        int w = warp * 8 + wi;
        const float4* mp = (const float4*)(Mb + w * N_ + ch * 256);
        float a0 = 0.f, a1 = 0.f, a2 = 0.f, a3 = 0.f;
#pragma unroll
        for (int nn = 0; nn < 2; nn++) {
            int q = lane + nn * 32;
            float4 m4 = mp[q];
            float4 r0 = ((const float4*)se[0])[q];
            float4 r1 = ((const float4*)se[1])[q];
            float4 r2 = ((const float4*)se[2])[q];
            float4 r3 = ((const float4*)se[3])[q];
            a0 += m4.x * r0.x + m4.y * r0.y + m4.z * r0.z + m4.w * r0.w;
            a1 += m4.x * r1.x + m4.y * r1.y + m4.z * r1.z + m4.w * r1.w;
            a2 += m4.x * r2.x + m4.y * r2.y + m4.z * r2.z + m4.w * r2.w;
            a3 += m4.x * r3.x + m4.y * r3.y + m4.z * r3.z + m4.w * r3.w;
        }
#pragma unroll
        for (int o = 16; o; o >>= 1) {
            a0 += __shfl_down_sync(0xffffffffu, a0, o);
            a1 += __shfl_down_sync(0xffffffffu, a1, o);
            a2 += __shfl_down_sync(0xffffffffu, a2, o);
            a3 += __shfl_down_sync(0xffffffffu, a3, o);
        }
        if (lane == 0) {
            float* rp = g_rvpart + (ch * B_ + b) * 256;
            rp[0 * 64 + w] = a0; rp[64 + w] = a1; rp[128 + w] = a2; rp[192 + w] = a3;
        }
    }
}

// --- small: softmax finalize + scales + rwsum + usage + argmin partials ----
// grid (4 n-chunks of 512, 64 b), 256 threads; NO M traffic.
__global__ __launch_bounds__(256) void k_usage(const float* __restrict__ gamma_p) {
    int ch = blockIdx.x, b = blockIdx.y;
    int n0 = ch * 512;
    int tid = threadIdx.x;
    __shared__ float smv[256];
    __shared__ int   smi[256];
    __shared__ float sgmax[4], sginv[4];
    __shared__ float sscale[8][4];
    if (tid < 4) {
        int r = tid;
        float mx = -3.4e38f;
#pragma unroll
        for (int c = 0; c < 8; c++) mx = fmaxf(mx, g_pmax[(b * 8 + c) * 4 + r]);
        float sv = 0.f;
#pragma unroll
        for (int c = 0; c < 8; c++)
            sv += g_psum[(b * 8 + c) * 4 + r] * expf(g_pmax[(b * 8 + c) * 4 + r] - mx);
        sgmax[r] = mx;
        sginv[r] = 1.f / sv;
    }
    __syncthreads();
    if (tid < 32) {
        int r = tid & 3;
        float sc = expf(g_pmax[b * 32 + tid] - sgmax[r]) * sginv[r];
        sscale[tid >> 2][r] = sc;
        if (ch == 0) g_scale[b * 32 + tid] = sc;
    }
    __syncthreads();

    float gamma = *gamma_p;
    float lmin = 3.4e38f; int lidx = 0;
#pragma unroll
    for (int i = 0; i < 2; i++) {
        int n = n0 + tid + i * 256;
        int c8 = n >> 8;
        float4 e4 = *(const float4*)&g_eraw[(b * N_ + n) * 4];
        float rwsum = e4.x * sscale[c8][0] + e4.y * sscale[c8][1] +
                      e4.z * sscale[c8][2] + e4.w * sscale[c8][3];
        g_rwsum[b * N_ + n] = rwsum;
        float un = gamma * g_usage[b * N_ + n] + rwsum + g_ww[b * N_ + n];
        g_usage[b * N_ + n] = un;
        if (un < lmin) { lmin = un; lidx = n; }
    }
    smv[tid] = lmin; smi[tid] = lidx;
    __syncthreads();
    for (int s = 128; s > 0; s >>= 1) {
        if (tid < s) {
            float v2 = smv[tid + s]; int i2 = smi[tid + s];
            if (v2 < smv[tid] || (v2 == smv[tid] && i2 < smi[tid])) { smv[tid] = v2; smi[tid] = i2; }
        }
        __syncthreads();
    }
    if (tid == 0) { g_aminv[b * 4 + ch] = smv[0]; g_amini[b * 4 + ch] = smi[0]; }
}

// ------------------------- launch ------------------------------------------
extern "C" void kernel_launch(void* const* d_in, const int* in_sizes, int n_in,
                              void* d_out, int out_size) {
    const float* x_seq = (const float*)d_in[0];
    const float* Wih   = (const float*)d_in[1];
    const float* Whh   = (const float*)d_in[2];
    const float* bih   = (const float*)d_in[3];
    const float* bhh   = (const float*)d_in[4];
    const float* Wout  = (const float*)d_in[5];
    const float* bout  = (const float*)d_in[6];
    const float* Wkey  = (const float*)d_in[7];
    const float* bkey  = (const float*)d_in[8];
    const float* alpha = (const float*)d_in[9];
    const float* gamma = (const float*)d_in[10];
    float* out = (float*)d_out;

    k_t1<<<(KTOT_ * G_ + 255) / 256, 256>>>(Wih, Whh);
    k_t2<<<(H_ * 448 + 255) / 256, 256>>>(Wout, bout, Wkey, bkey);
    k_init<<<(B_ * W_ * N_) / 256, 256>>>();

    for (int t = 0; t < T_; t++) {
        int par = t & 1;
        k_gates<<<dim3(G_ / JT_, KSPLIT_, B_ / BS_), JT_>>>(x_seq, t);
        k_cell<<<(B_ * H_) / 256, 256>>>(bih, bhh);
        k_headg<<<dim3(4, 8, B_ / BS_), 112>>>();
        k_simwrite<<<dim3(8, B_), 256>>>(out, t, alpha, par);
        k_usage<<<dim3(4, B_), 256>>>(gamma);
    }
}

// round 7
// speedup vs baseline: 1.0643x; 1.0401x over previous
#include <cuda_runtime.h>
#include <math.h>

// Problem constants
#define T_     128
#define B_     64
#define IN_    128
#define H_     512
#define G_     2048   // 4*H
#define N_     2048
#define W_     64
#define R_     4
#define OUT_   128
#define KEYS_  320    // (R+1)*W
#define CTRL_  384    // IN + R*W
#define KTOT_  896    // CTRL + H
#define KSPLIT_ 16
#define KC_    56     // KTOT/KSPLIT
#define JT_    128
#define BS_    16     // batch elements per gates block
#define EPS_   1e-8f

// ------------------------- persistent device state -------------------------
__device__ float g_WT[KTOT_ * G_];        // combined [Wih;Whh] transposed: [k][j]
__device__ float g_WT2[H_ * 448];         // combined [Wout;Wkey] transposed: [k][j]
__device__ float g_bc[448];               // combined [bout;bkey]
__device__ float g_h[B_ * H_];
__device__ float g_c[B_ * H_];
__device__ float g_M[2][B_ * W_ * N_];    // [par][b][w][n]  (n fastest!)
__device__ float g_usage[B_ * N_];
__device__ float g_gpart[KSPLIT_ * B_ * G_];
__device__ float g_hpart[8 * B_ * 448];   // heads partials [kc][b][j]
__device__ float g_kinv[B_ * R_];         // 1/(||read_key||+eps)
__device__ float g_eraw[B_ * N_ * R_];    // exp(sim - cmax_ch), [b][n][r]
__device__ float g_rwsum[B_ * N_];        // normalized sum_r rw[r][n]
__device__ float g_ww[B_ * N_];
__device__ float g_pmax[B_ * 8 * 4];      // softmax chunk partial max  [b][ch][r]
__device__ float g_psum[B_ * 8 * 4];      // softmax chunk partial sum  [b][ch][r]
__device__ float g_scale[B_ * 8 * 4];     // exp(cmax-gmax)/gsum        [b][ch][r]
__device__ float g_rvpart[8 * B_ * 256];  // unnormalized rv partials [ch][b][r*64+w]
__device__ float g_aminv[B_ * 4];
__device__ int   g_amini[B_ * 4];

// ------------------------- weight prep -------------------------
__global__ void k_t1(const float* __restrict__ Wih, const float* __restrict__ Whh) {
    int idx = blockIdx.x * 256 + threadIdx.x;
    if (idx >= KTOT_ * G_) return;
    int k = idx / G_, j = idx % G_;
    g_WT[idx] = (k < CTRL_) ? Wih[j * CTRL_ + k] : Whh[j * H_ + (k - CTRL_)];
}

__global__ void k_t2(const float* __restrict__ Wout, const float* __restrict__ bout,
                     const float* __restrict__ Wkey, const float* __restrict__ bkey) {
    int idx = blockIdx.x * 256 + threadIdx.x;
    if (idx < H_ * 448) {
        int k = idx / 448, j = idx % 448;
        g_WT2[idx] = (j < OUT_) ? Wout[j * H_ + k] : Wkey[(j - OUT_) * H_ + k];
    }
    if (idx < 448) g_bc[idx] = (idx < OUT_) ? bout[idx] : bkey[idx - OUT_];
}

__global__ void k_init() {
    int idx = blockIdx.x * 256 + threadIdx.x;            // covers B*W*N = 8388608
    g_M[0][idx] = 1e-6f;
    if (idx < B_ * N_ * R_)  g_eraw[idx] = 0.f;
    if (idx < B_ * N_)     { g_usage[idx] = 0.f; g_ww[idx] = 0.f; g_rwsum[idx] = 0.f; }
    if (idx < B_ * H_)     { g_h[idx] = 0.f; g_c[idx] = 0.f; }
    if (idx < 8 * B_ * 256)  g_rvpart[idx] = 0.f;
    if (idx < B_ * 8 * 4)    g_scale[idx] = 0.f;
    if (idx < B_ * 4)      { g_aminv[idx] = 0.f; g_amini[idx] = (idx & 3) * 512; }
}

// ------------------------- gates GEMM (split-K 16, split-B 4) --------------
// grid (16 j-tiles, 16 k-chunks, 4 b-splits) = 1024 blocks, 128 threads.
// Thread (tj,tb) computes a 4j x 4b register tile.
__global__ __launch_bounds__(128) void k_gates(const float* __restrict__ x_seq, int t) {
    __shared__ __align__(16) float Xs[KC_][BS_];
    __shared__ __align__(16) float Ws[8][JT_];
    int tid = threadIdx.x;
    int tj  = tid & 31;     // 32 j-groups of 4
    int tb  = tid >> 5;     // 4 b-groups of 4
    int j0  = blockIdx.x * JT_;
    int kc  = blockIdx.y;
    int k0  = kc * KC_;
    int b0  = blockIdx.z * BS_;

    for (int idx = tid; idx < BS_ * KC_; idx += 128) {
        int kk = idx / BS_, b = idx % BS_;
        int k = k0 + kk;
        int bg = b0 + b;
        float v;
        if (k < IN_)        v = x_seq[(t * B_ + bg) * IN_ + k];
        else if (k < CTRL_) {
            int o = k - IN_;
            int r = o >> 6;
            v = 0.f;
#pragma unroll
            for (int ch = 0; ch < 8; ch++)
                v += g_rvpart[(ch * B_ + bg) * 256 + o] * g_scale[bg * 32 + ch * 4 + r];
        } else              v = g_h[bg * H_ + (k - CTRL_)];
        Xs[kk][b] = v;
    }
    __syncthreads();

    float4 acc[4];
#pragma unroll
    for (int i = 0; i < 4; i++) acc[i] = make_float4(0.f, 0.f, 0.f, 0.f);

    for (int ks = 0; ks < KC_; ks += 8) {
        if (ks) __syncthreads();
#pragma unroll
        for (int i = 0; i < 8; i++)
            Ws[i][tid] = g_WT[(k0 + ks + i) * G_ + j0 + tid];
        __syncthreads();
#pragma unroll
        for (int i = 0; i < 8; i++) {
            float4 w4 = *(const float4*)&Ws[i][tj * 4];
            float4 x4 = *(const float4*)&Xs[ks + i][tb * 4];
            acc[0].x += x4.x * w4.x; acc[0].y += x4.x * w4.y;
            acc[0].z += x4.x * w4.z; acc[0].w += x4.x * w4.w;
            acc[1].x += x4.y * w4.x; acc[1].y += x4.y * w4.y;
            acc[1].z += x4.y * w4.z; acc[1].w += x4.y * w4.w;
            acc[2].x += x4.z * w4.x; acc[2].y += x4.z * w4.y;
            acc[2].z += x4.z * w4.z; acc[2].w += x4.z * w4.w;
            acc[3].x += x4.w * w4.x; acc[3].y += x4.w * w4.y;
            acc[3].z += x4.w * w4.z; acc[3].w += x4.w * w4.w;
        }
    }
    float* gp = g_gpart + kc * (B_ * G_);
#pragma unroll
    for (int bb = 0; bb < 4; bb++)
        *(float4*)&gp[(b0 + tb * 4 + bb) * G_ + j0 + tj * 4] = acc[bb];
}

// ------------------------- reduce partials + LSTM cell ---------------------
__global__ void k_cell(const float* __restrict__ bih, const float* __restrict__ bhh) {
    int gid = blockIdx.x * blockDim.x + threadIdx.x;   // B*H = 32768
    int b = gid >> 9, u = gid & 511;
    float s[4];
#pragma unroll
    for (int q = 0; q < 4; q++) {
        int col = q * H_ + u;
        float v = bih[col] + bhh[col];
#pragma unroll
        for (int kc = 0; kc < KSPLIT_; kc++)
            v += g_gpart[kc * (B_ * G_) + b * G_ + col];
        s[q] = v;
    }
    float ig = 1.f / (1.f + expf(-s[0]));
    float fg = 1.f / (1.f + expf(-s[1]));
    float gg = tanhf(s[2]);
    float og = 1.f / (1.f + expf(-s[3]));
    float c  = fg * g_c[gid] + ig * gg;
    g_c[gid] = c;
    g_h[gid] = og * tanhf(c);
}

// ------------------------- heads GEMM (split-K, split-B) -------------------
__global__ __launch_bounds__(112) void k_headg() {
    __shared__ __align__(16) float Hs[64][BS_];
    __shared__ float Ws[8][112];
    int tid = threadIdx.x;
    int j   = blockIdx.x * 112 + tid;
    int k0  = blockIdx.y * 64;
    int b0  = blockIdx.z * BS_;

    for (int idx = tid; idx < BS_ * 64; idx += 112) {
        int kk = idx / BS_, b = idx % BS_;
        Hs[kk][b] = g_h[(b0 + b) * H_ + k0 + kk];
    }
    __syncthreads();

    float4 acc[4];
#pragma unroll
    for (int i = 0; i < 4; i++) acc[i] = make_float4(0.f, 0.f, 0.f, 0.f);

    for (int ks = 0; ks < 64; ks += 8) {
        if (ks) __syncthreads();
#pragma unroll
        for (int i = 0; i < 8; i++)
            Ws[i][tid] = g_WT2[(k0 + ks + i) * 448 + j];
        __syncthreads();
#pragma unroll
        for (int i = 0; i < 8; i++) {
            float w = Ws[i][tid];
            const float4* xrow = (const float4*)&Hs[ks + i][0];
#pragma unroll
            for (int b4 = 0; b4 < 4; b4++) {
                float4 x = xrow[b4];
                acc[b4].x += x.x * w; acc[b4].y += x.y * w;
                acc[b4].z += x.z * w; acc[b4].w += x.w * w;
            }
        }
    }
    float* hp = g_hpart + blockIdx.y * (B_ * 448);
#pragma unroll
    for (int b4 = 0; b4 < 4; b4++) {
        hp[(b0 + 4 * b4 + 0) * 448 + j] = acc[b4].x;
        hp[(b0 + 4 * b4 + 1) * 448 + j] = acc[b4].y;
        hp[(b0 + 4 * b4 + 2) * 448 + j] = acc[b4].z;
        hp[(b0 + 4 * b4 + 3) * 448 + j] = acc[b4].w;
    }
}

// ---- mega: keys reduce + out + norms + sims + softmax partials + M write
// ---- + unnormalized read-vec partials.  grid (8 n-chunks, 64 b), 256 thr.
__global__ __launch_bounds__(256) void k_simwrite(float* __restrict__ out, int t,
                                                  const float* __restrict__ alpha_p, int par) {
    int b = blockIdx.y;
    int ch = blockIdx.x;
    int tid = threadIdx.x;
    int n = ch * 256 + tid;
    __shared__ float skey[KEYS_];
    __shared__ float skinv[4];
    __shared__ float s_sa;
    __shared__ int s_amin;
    __shared__ float sred[8][4];
    __shared__ float sbmax[4];
    __shared__ __align__(16) float se[4][256];

    // keys reduce from hpart
    for (int i = tid; i < KEYS_; i += 256) {
        float v = g_bc[OUT_ + i];
#pragma unroll
        for (int kc = 0; kc < 8; kc++)
            v += g_hpart[kc * (B_ * 448) + b * 448 + OUT_ + i];
        skey[i] = v;
    }
    // out write (once, by ch==0 blocks)
    if (ch == 0 && tid < OUT_) {
        float v = g_bc[tid];
#pragma unroll
        for (int kc = 0; kc < 8; kc++)
            v += g_hpart[kc * (B_ * 448) + b * 448 + tid];
        out[(t * B_ + b) * OUT_ + tid] = v;
    }
    if (tid == 254) s_sa = 1.f / (1.f + expf(-*alpha_p));
    if (tid == 255) {
        float bv = g_aminv[b * 4]; int bi = g_amini[b * 4];
#pragma unroll
        for (int c2 = 1; c2 < 4; c2++) {
            float v2 = g_aminv[b * 4 + c2]; int i2 = g_amini[b * 4 + c2];
            if (v2 < bv || (v2 == bv && i2 < bi)) { bv = v2; bi = i2; }
        }
        s_amin = bi;
    }
    __syncthreads();
    // key norms
    if (tid < 128) {
        int r = tid >> 5, lane = tid & 31;
        float a = skey[r * 64 + lane], c2 = skey[r * 64 + lane + 32];
        float ssq = a * a + c2 * c2;
#pragma unroll
        for (int o = 16; o; o >>= 1) ssq += __shfl_down_sync(0xffffffffu, ssq, o);
        if (lane == 0) skinv[r] = 1.f / (sqrtf(ssq) + EPS_);
    }
    __syncthreads();

    const float* Mold = g_M[par]     + b * (W_ * N_) + n;
    float*       Mnew = g_M[par ^ 1] + b * (W_ * N_) + n;
    float m[64];
    float ss = 0.f, d0 = 0.f, d1 = 0.f, d2 = 0.f, d3 = 0.f;
#pragma unroll
    for (int w = 0; w < 64; w++) {
        float mv = Mold[w * N_];
        m[w] = mv;
        ss += mv * mv;
        d0 += mv * skey[w];       d1 += mv * skey[64 + w];
        d2 += mv * skey[128 + w]; d3 += mv * skey[192 + w];
    }
    float minv = 1.f / (sqrtf(ss) + EPS_);
    float s4[4];
    s4[0] = d0 * skinv[0] * minv;
    s4[1] = d1 * skinv[1] * minv;
    s4[2] = d2 * skinv[2] * minv;
    s4[3] = d3 * skinv[3] * minv;

    // chunk softmax partials: max & sum(exp(v-max)) over 256 n, 4 r
    int warp = tid >> 5, lane = tid & 31;
#pragma unroll
    for (int r = 0; r < 4; r++) {
        float mv = s4[r];
#pragma unroll
        for (int o = 16; o; o >>= 1) mv = fmaxf(mv, __shfl_xor_sync(0xffffffffu, mv, o));
        if (lane == 0) sred[warp][r] = mv;
    }
    __syncthreads();
    if (tid < 4) {
        float mv = sred[0][tid];
#pragma unroll
        for (int w2 = 1; w2 < 8; w2++) mv = fmaxf(mv, sred[w2][tid]);
        sbmax[tid] = mv;
    }
    __syncthreads();
    float e4[4];
#pragma unroll
    for (int r = 0; r < 4; r++) {
        float e = expf(s4[r] - sbmax[r]);
        e4[r] = e;
        se[r][tid] = e;
#pragma unroll
        for (int o = 16; o; o >>= 1) e += __shfl_xor_sync(0xffffffffu, e, o);
        if (lane == 0) sred[warp][r] = e;
    }
    *(float4*)&g_eraw[(b * N_ + n) * 4] = make_float4(e4[0], e4[1], e4[2], e4[3]);
    __syncthreads();
    if (tid < 4) {
        float sv = sred[0][tid];
#pragma unroll
        for (int w2 = 1; w2 < 8; w2++) sv += sred[w2][tid];
        g_pmax[(b * 8 + ch) * 4 + tid] = sbmax[tid];
        g_psum[(b * 8 + ch) * 4 + tid] = sv;
    }

    // M rewrite + ww (uses previous step's normalized rwsum)
    float rs = g_rwsum[b * N_ + n];
    float lu = (n == s_amin) ? 1.f : 0.f;
    float sa = s_sa;
    float ww = sa * rs + (1.f - sa) * lu;
    g_ww[b * N_ + n] = ww;
    float keep = 1.f - lu;
#pragma unroll
    for (int w = 0; w < 64; w++)
        Mnew[w * N_] = m[w] * keep + ww * skey[256 + w];

    // unnormalized read-vec partials over this chunk (L1/L2-hot M re-read)
    const float* Mb = g_M[par] + b * (W_ * N_);
#pragma unroll
    for (int wi = 0; wi < 8; wi++) {
        int w = warp * 8 + wi;
        const float4* mp = (const float4*)(Mb + w * N_ + ch * 256);
        float a0 = 0.f, a1 = 0.f, a2 = 0.f, a3 = 0.f;
#pragma unroll
        for (int nn = 0; nn < 2; nn++) {
            int q = lane + nn * 32;
            float4 m4 = mp[q];
            float4 r0 = ((const float4*)se[0])[q];
            float4 r1 = ((const float4*)se[1])[q];
            float4 r2 = ((const float4*)se[2])[q];
            float4 r3 = ((const float4*)se[3])[q];
            a0 += m4.x * r0.x + m4.y * r0.y + m4.z * r0.z + m4.w * r0.w;
            a1 += m4.x * r1.x + m4.y * r1.y + m4.z * r1.z + m4.w * r1.w;
            a2 += m4.x * r2.x + m4.y * r2.y + m4.z * r2.z + m4.w * r2.w;
            a3 += m4.x * r3.x + m4.y * r3.y + m4.z * r3.z + m4.w * r3.w;
        }
#pragma unroll
        for (int o = 16; o; o >>= 1) {
            a0 += __shfl_down_sync(0xffffffffu, a0, o);
            a1 += __shfl_down_sync(0xffffffffu, a1, o);
            a2 += __shfl_down_sync(0xffffffffu, a2, o);
            a3 += __shfl_down_sync(0xffffffffu, a3, o);
        }
        if (lane == 0) {
            float* rp = g_rvpart + (ch * B_ + b) * 256;
            rp[0 * 64 + w] = a0; rp[64 + w] = a1; rp[128 + w] = a2; rp[192 + w] = a3;
        }
    }
}

// --- small: softmax finalize + scales + rwsum + usage + argmin partials ----
// grid (4 n-chunks of 512, 64 b), 256 threads; NO M traffic.
__global__ __launch_bounds__(256) void k_usage(const float* __restrict__ gamma_p) {
    int ch = blockIdx.x, b = blockIdx.y;
    int n0 = ch * 512;
    int tid = threadIdx.x;
    __shared__ float smv[256];
    __shared__ int   smi[256];
    __shared__ float sgmax[4], sginv[4];
    __shared__ float sscale[8][4];
    if (tid < 4) {
        int r = tid;
        float mx = -3.4e38f;
#pragma unroll
        for (int c = 0; c < 8; c++) mx = fmaxf(mx, g_pmax[(b * 8 + c) * 4 + r]);
        float sv = 0.f;
#pragma unroll
        for (int c = 0; c < 8; c++)
            sv += g_psum[(b * 8 + c) * 4 + r] * expf(g_pmax[(b * 8 + c) * 4 + r] - mx);
        sgmax[r] = mx;
        sginv[r] = 1.f / sv;
    }
    __syncthreads();
    if (tid < 32) {
        int r = tid & 3;
        float sc = expf(g_pmax[b * 32 + tid] - sgmax[r]) * sginv[r];
        sscale[tid >> 2][r] = sc;
        if (ch == 0) g_scale[b * 32 + tid] = sc;
    }
    __syncthreads();

    float gamma = *gamma_p;
    float lmin = 3.4e38f; int lidx = 0;
#pragma unroll
    for (int i = 0; i < 2; i++) {
        int n = n0 + tid + i * 256;
        int c8 = n >> 8;
        float4 e4 = *(const float4*)&g_eraw[(b * N_ + n) * 4];
        float rwsum = e4.x * sscale[c8][0] + e4.y * sscale[c8][1] +
                      e4.z * sscale[c8][2] + e4.w * sscale[c8][3];
        g_rwsum[b * N_ + n] = rwsum;
        float un = gamma * g_usage[b * N_ + n] + rwsum + g_ww[b * N_ + n];
        g_usage[b * N_ + n] = un;
        if (un < lmin) { lmin = un; lidx = n; }
    }
    smv[tid] = lmin; smi[tid] = lidx;
    __syncthreads();
    for (int s = 128; s > 0; s >>= 1) {
        if (tid < s) {
            float v2 = smv[tid + s]; int i2 = smi[tid + s];
            if (v2 < smv[tid] || (v2 == smv[tid] && i2 < smi[tid])) { smv[tid] = v2; smi[tid] = i2; }
        }
        __syncthreads();
    }
    if (tid == 0) { g_aminv[b * 4 + ch] = smv[0]; g_amini[b * 4 + ch] = smi[0]; }
}

// ------------------------- launch ------------------------------------------
extern "C" void kernel_launch(void* const* d_in, const int* in_sizes, int n_in,
                              void* d_out, int out_size) {
    const float* x_seq = (const float*)d_in[0];
    const float* Wih   = (const float*)d_in[1];
    const float* Whh   = (const float*)d_in[2];
    const float* bih   = (const float*)d_in[3];
    const float* bhh   = (const float*)d_in[4];
    const float* Wout  = (const float*)d_in[5];
    const float* bout  = (const float*)d_in[6];
    const float* Wkey  = (const float*)d_in[7];
    const float* bkey  = (const float*)d_in[8];
    const float* alpha = (const float*)d_in[9];
    const float* gamma = (const float*)d_in[10];
    float* out = (float*)d_out;

    k_t1<<<(KTOT_ * G_ + 255) / 256, 256>>>(Wih, Whh);
    k_t2<<<(H_ * 448 + 255) / 256, 256>>>(Wout, bout, Wkey, bkey);
    k_init<<<(B_ * W_ * N_) / 256, 256>>>();

    for (int t = 0; t < T_; t++) {
        int par = t & 1;
        k_gates<<<dim3(G_ / JT_, KSPLIT_, B_ / BS_), JT_>>>(x_seq, t);
        k_cell<<<(B_ * H_) / 256, 256>>>(bih, bhh);
        k_headg<<<dim3(4, 8, B_ / BS_), 112>>>();
        k_simwrite<<<dim3(8, B_), 256>>>(out, t, alpha, par);
        k_usage<<<dim3(4, B_), 256>>>(gamma);
    }
}